// round 15
// baseline (speedup 1.0000x reference)
#include <cuda_runtime.h>
#include <cuda_bf16.h>
#include <cstdint>

// Device-global scratch (no allocations). Zero-init; last block resets.
__device__ double        g_acc       = 0.0;
__device__ unsigned int  g_acc_count = 0;

#define LOG2E 1.44269504088896340736f
#define LN2   0.69314718055994530942f

__device__ __forceinline__ float rcp_approx(float x) {
    float r; asm("rcp.approx.f32 %0, %1;" : "=f"(r) : "f"(x)); return r;
}
__device__ __forceinline__ float ex2_approx(float x) {
    float r; asm("ex2.approx.f32 %0, %1;" : "=f"(r) : "f"(x)); return r;
}
__device__ __forceinline__ float lg2_approx(float x) {
    float r; asm("lg2.approx.f32 %0, %1;" : "=f"(r) : "f"(x)); return r;
}

// 256-bit global loads (sm_100+: LDG.E.256)
__device__ __forceinline__ void ldg256_f32(const float* p, float* v) {
    asm("ld.global.nc.v8.f32 {%0,%1,%2,%3,%4,%5,%6,%7}, [%8];"
        : "=f"(v[0]), "=f"(v[1]), "=f"(v[2]), "=f"(v[3]),
          "=f"(v[4]), "=f"(v[5]), "=f"(v[6]), "=f"(v[7])
        : "l"(p));
}
__device__ __forceinline__ void ldg256_s32(const int* p, int* v) {
    asm("ld.global.nc.v8.u32 {%0,%1,%2,%3,%4,%5,%6,%7}, [%8];"
        : "=r"(v[0]), "=r"(v[1]), "=r"(v[2]), "=r"(v[3]),
          "=r"(v[4]), "=r"(v[5]), "=r"(v[6]), "=r"(v[7])
        : "l"(p));
}

// tbl[p*3+t] = { 1.5*P[p][t],  0.1*(p!=t),  class_w[t]*ln2,  0 }
__device__ __forceinline__ void row_loss(float l0, float l1, float l2, int t,
                                         const float4* __restrict__ tbl,
                                         float& acc, float& accP)
{
    // exact first-occurrence argmax (strict > matches jnp.argmax)
    const bool  pa  = (l1 > l0);
    const float m01 = fmaxf(l0, l1);
    const bool  pb  = (l2 > m01);
    const float m   = fmaxf(m01, l2);

    const int p3  = pb ? 6 : (pa ? 3 : 0);     // p * 3
    const float4 e = tbl[p3 + t];              // {pen15, confw, aln2, -}

    // log2-domain shifted deltas; max lane is exactly 0 -> exp = 1
    const float nmK = -m * LOG2E;
    const float s0 = fmaf(l0, LOG2E, nmK);
    const float s1 = fmaf(l1, LOG2E, nmK);
    const float s2 = fmaf(l2, LOG2E, nmK);

    const float e0 = ex2_approx(s0);
    const float e1 = ex2_approx(s1);
    const float e2 = ex2_approx(s2);
    const float S    = e0 + e1 + e2;
    const float rcpS = rcp_approx(S);          // == max prob (exp at argmax is 1)

    // pt = prob[target]; ce2 = -log2(pt)
    const float et = (t == 0) ? e0 : ((t == 1) ? e1 : e2);
    const float pt = et * rcpS;
    const float nq = lg2_approx(pt);           // log2(pt) <= 0
    const float omp = 1.0f - pt;

    const float w  = e.z * omp;                // alpha*ln2 * (1-pt)
    acc  = fmaf(w * omp, -nq, acc);            // focal (negation free in FMA)
    acc  = fmaf(e.y, rcpS, acc);               // 0.1*(p!=t)*max_prob
    accP += e.x;                               // 1.5*penalty
}

__global__ void __launch_bounds__(256, 4)
trading_loss_kernel(const float* __restrict__ logits,
                    const int*   __restrict__ targets,
                    const float* __restrict__ class_w,
                    float*       __restrict__ out,
                    int npairs, int ngroups, float inv_n, int nblocks)
{
    __shared__ float4 tbl[9];
    __shared__ float  warp_sums[8];
    __shared__ bool   is_last;

    if (threadIdx.x < 9) {
        const int p = threadIdx.x / 3;
        const int t = threadIdx.x - p * 3;
        int d = p - t; d = (d < 0) ? -d : d;
        const float pen15 = 0.75f * (float)d + ((d == 2) ? 0.75f : 0.0f);
        const float confw = (d != 0) ? 0.1f : 0.0f;
        tbl[threadIdx.x] = make_float4(pen15, confw, class_w[t] * LN2, 0.0f);
    }
    __syncthreads();

    float acc0 = 0.0f, acc1 = 0.0f, accP = 0.0f;

    const int tid    = blockIdx.x * blockDim.x + threadIdx.x;
    const int stride = gridDim.x * blockDim.x;

    // One PAIR of groups per iteration = 8 rows:
    //   96 B logits  = 3x LDG.256   (float8)
    //   32 B targets = 1x LDG.256   (int8)
    for (int q = tid; q < npairs; q += stride) {
        float f[24];
        int   tg[8];
        const float* lp = logits + (size_t)q * 24;
        ldg256_f32(lp +  0, f +  0);
        ldg256_f32(lp +  8, f +  8);
        ldg256_f32(lp + 16, f + 16);
        ldg256_s32(targets + (size_t)q * 8, tg);

        #pragma unroll
        for (int r = 0; r < 8; r += 2) {
            row_loss(f[3*r + 0], f[3*r + 1], f[3*r + 2], tg[r],     tbl, acc0, accP);
            row_loss(f[3*r + 3], f[3*r + 4], f[3*r + 5], tg[r + 1], tbl, acc1, accP);
        }
    }

    // remainder groups (ngroups % 2) — empty for the bench shape
    for (int g = npairs * 2 + tid; g < ngroups; g += stride) {
        const float4* lp = reinterpret_cast<const float4*>(logits) + (size_t)g * 3;
        const float4 a0 = __ldg(lp + 0);
        const float4 a1 = __ldg(lp + 1);
        const float4 a2 = __ldg(lp + 2);
        const int4   t4 = __ldg(reinterpret_cast<const int4*>(targets) + g);
        row_loss(a0.x, a0.y, a0.z, t4.x, tbl, acc0, accP);
        row_loss(a0.w, a1.x, a1.y, t4.y, tbl, acc1, accP);
        row_loss(a1.z, a1.w, a2.x, t4.z, tbl, acc0, accP);
        row_loss(a2.y, a2.z, a2.w, t4.w, tbl, acc1, accP);
    }

    float acc = (acc0 + acc1) + accP;

    // ---- block reduction ----
    #pragma unroll
    for (int off = 16; off > 0; off >>= 1)
        acc += __shfl_xor_sync(0xFFFFFFFFu, acc, off);

    const int lane = threadIdx.x & 31;
    const int wid  = threadIdx.x >> 5;
    if (lane == 0) warp_sums[wid] = acc;
    __syncthreads();

    if (wid == 0) {
        float v = (lane < (blockDim.x >> 5)) ? warp_sums[lane] : 0.0f;
        #pragma unroll
        for (int off = 4; off > 0; off >>= 1)
            v += __shfl_xor_sync(0xFFFFFFFFu, v, off);
        if (lane == 0) {
            atomicAdd(&g_acc, (double)v);
            __threadfence();
            unsigned int ticket = atomicAdd(&g_acc_count, 1u);
            is_last = (ticket == (unsigned int)nblocks - 1u);
        }
    }
    __syncthreads();

    if (is_last && threadIdx.x == 0) {
        double total = g_acc;
        out[0] = (float)(total * (double)inv_n);
        g_acc = 0.0;
        g_acc_count = 0u;
    }
}

extern "C" void kernel_launch(void* const* d_in, const int* in_sizes, int n_in,
                              void* d_out, int out_size)
{
    const float* logits  = (const float*)d_in[0];
    const int*   targets = (const int*)d_in[1];
    const float* class_w = (const float*)d_in[2];
    float*       out     = (float*)d_out;

    const int batch   = in_sizes[1];       // targets element count = B
    const int ngroups = batch / 4;         // 4 rows per float4-group
    const int npairs  = ngroups / 2;       // 8 rows per iteration unit

    const int threads = 256;
    int blocks = 152 * 4;                  // single wave at 4 blocks/SM (GB300)
    int maxb   = (npairs + threads - 1) / threads;
    if (blocks > maxb) blocks = maxb;
    if (blocks < 1) blocks = 1;

    trading_loss_kernel<<<blocks, threads>>>(logits, targets, class_w, out,
                                             npairs, ngroups,
                                             1.0f / (float)batch, blocks);
}

// round 16
// speedup vs baseline: 1.0590x; 1.0590x over previous
#include <cuda_runtime.h>
#include <cuda_bf16.h>
#include <cstdint>

// Device-global scratch (no allocations). Zero-init; last block resets.
__device__ double        g_acc       = 0.0;
__device__ unsigned int  g_acc_count = 0;

#define LOG2E 1.44269504088896340736f
#define LN2   0.69314718055994530942f

__device__ __forceinline__ float rcp_approx(float x) {
    float r; asm("rcp.approx.f32 %0, %1;" : "=f"(r) : "f"(x)); return r;
}
__device__ __forceinline__ float ex2_approx(float x) {
    float r; asm("ex2.approx.f32 %0, %1;" : "=f"(r) : "f"(x)); return r;
}
__device__ __forceinline__ float lg2_approx(float x) {
    float r; asm("lg2.approx.f32 %0, %1;" : "=f"(r) : "f"(x)); return r;
}

// tbl[p*3+t] = { 1.5*P[p][t],  0.1*(p!=t),  class_w[t]*ln2,  0 }
__device__ __forceinline__ void row_loss(float l0, float l1, float l2, int t,
                                         const float4* __restrict__ tbl,
                                         float& acc, float& accP)
{
    // exact first-occurrence argmax (strict > matches jnp.argmax)
    const bool  pa  = (l1 > l0);
    const float m01 = fmaxf(l0, l1);
    const bool  pb  = (l2 > m01);
    const float m   = fmaxf(m01, l2);

    const int p3  = pb ? 6 : (pa ? 3 : 0);     // p * 3
    const float4 e = tbl[p3 + t];              // {pen15, confw, aln2, -}

    // log2-domain shifted deltas; max lane is exactly 0 -> exp = 1
    const float nmK = -m * LOG2E;
    const float s0 = fmaf(l0, LOG2E, nmK);
    const float s1 = fmaf(l1, LOG2E, nmK);
    const float s2 = fmaf(l2, LOG2E, nmK);

    const float e0 = ex2_approx(s0);
    const float e1 = ex2_approx(s1);
    const float e2 = ex2_approx(s2);
    const float S    = e0 + e1 + e2;
    const float rcpS = rcp_approx(S);          // == max prob (exp at argmax is 1)

    // pt = prob[target]; ce2 = -log2(pt)
    const float et = (t == 0) ? e0 : ((t == 1) ? e1 : e2);
    const float pt = et * rcpS;
    const float nq = lg2_approx(pt);           // log2(pt) <= 0
    const float omp = 1.0f - pt;

    const float w  = e.z * omp;                // alpha*ln2 * (1-pt)
    acc  = fmaf(w * omp, -nq, acc);            // focal (negation free in FMA)
    acc  = fmaf(e.y, rcpS, acc);               // 0.1*(p!=t)*max_prob
    accP += e.x;                               // 1.5*penalty
}

__global__ void __launch_bounds__(256, 6)
trading_loss_kernel(const float* __restrict__ logits,
                    const int*   __restrict__ targets,
                    const float* __restrict__ class_w,
                    float*       __restrict__ out,
                    int ngroups, float inv_n, int nblocks)
{
    __shared__ float4 tbl[9];
    __shared__ float  warp_sums[8];
    __shared__ bool   is_last;

    const int tid    = blockIdx.x * blockDim.x + threadIdx.x;
    const int stride = gridDim.x * blockDim.x;

    const float4* lbase = reinterpret_cast<const float4*>(logits);
    const int4*   tbase = reinterpret_cast<const int4*>(targets);

    // ---- issue the FIRST group's streaming loads before anything else ----
    // Their DRAM round-trip overlaps the class_w load, table build and barrier.
    const bool have0 = (tid < ngroups);
    float4 a0, a1, a2; int4 t4;
    if (have0) {
        a0 = __ldg(lbase + (size_t)tid * 3 + 0);
        a1 = __ldg(lbase + (size_t)tid * 3 + 1);
        a2 = __ldg(lbase + (size_t)tid * 3 + 2);
        t4 = __ldg(tbase + tid);
    }

    if (threadIdx.x < 9) {
        const int p = threadIdx.x / 3;
        const int t = threadIdx.x - p * 3;
        int d = p - t; d = (d < 0) ? -d : d;
        const float pen15 = 0.75f * (float)d + ((d == 2) ? 0.75f : 0.0f);
        const float confw = (d != 0) ? 0.1f : 0.0f;
        tbl[threadIdx.x] = make_float4(pen15, confw, class_w[t] * LN2, 0.0f);
    }
    __syncthreads();

    float acc0 = 0.0f, acc1 = 0.0f, accP = 0.0f;

    // peeled first iteration
    if (have0) {
        row_loss(a0.x, a0.y, a0.z, t4.x, tbl, acc0, accP);
        row_loss(a0.w, a1.x, a1.y, t4.y, tbl, acc1, accP);
        row_loss(a1.z, a1.w, a2.x, t4.z, tbl, acc0, accP);
        row_loss(a2.y, a2.z, a2.w, t4.w, tbl, acc1, accP);
    }

    // steady state — identical body to the champion kernel
    for (int g = tid + stride; g < ngroups; g += stride) {
        const float4 b0 = __ldg(lbase + (size_t)g * 3 + 0);
        const float4 b1 = __ldg(lbase + (size_t)g * 3 + 1);
        const float4 b2 = __ldg(lbase + (size_t)g * 3 + 2);
        const int4   u4 = __ldg(tbase + g);

        row_loss(b0.x, b0.y, b0.z, u4.x, tbl, acc0, accP);
        row_loss(b0.w, b1.x, b1.y, u4.y, tbl, acc1, accP);
        row_loss(b1.z, b1.w, b2.x, u4.z, tbl, acc0, accP);
        row_loss(b2.y, b2.z, b2.w, u4.w, tbl, acc1, accP);
    }

    float acc = (acc0 + acc1) + accP;

    // ---- block reduction ----
    #pragma unroll
    for (int off = 16; off > 0; off >>= 1)
        acc += __shfl_xor_sync(0xFFFFFFFFu, acc, off);

    const int lane = threadIdx.x & 31;
    const int wid  = threadIdx.x >> 5;
    if (lane == 0) warp_sums[wid] = acc;
    __syncthreads();

    if (wid == 0) {
        float v = (lane < (blockDim.x >> 5)) ? warp_sums[lane] : 0.0f;
        #pragma unroll
        for (int off = 4; off > 0; off >>= 1)
            v += __shfl_xor_sync(0xFFFFFFFFu, v, off);
        if (lane == 0) {
            atomicAdd(&g_acc, (double)v);
            __threadfence();
            unsigned int ticket = atomicAdd(&g_acc_count, 1u);
            is_last = (ticket == (unsigned int)nblocks - 1u);
        }
    }
    __syncthreads();

    if (is_last && threadIdx.x == 0) {
        double total = g_acc;
        out[0] = (float)(total * (double)inv_n);
        g_acc = 0.0;
        g_acc_count = 0u;
    }
}

extern "C" void kernel_launch(void* const* d_in, const int* in_sizes, int n_in,
                              void* d_out, int out_size)
{
    const float* logits  = (const float*)d_in[0];
    const int*   targets = (const int*)d_in[1];
    const float* class_w = (const float*)d_in[2];
    float*       out     = (float*)d_out;

    const int batch   = in_sizes[1];       // targets element count = B
    const int ngroups = batch / 4;         // 4 rows per float4-group

    const int threads = 256;
    int blocks = 152 * 6;                  // single resident wave (GB300: 152 SMs)
    int maxb   = (ngroups + threads - 1) / threads;
    if (blocks > maxb) blocks = maxb;
    if (blocks < 1) blocks = 1;

    trading_loss_kernel<<<blocks, threads>>>(logits, targets, class_w, out,
                                             ngroups, 1.0f / (float)batch, blocks);
}